// round 15
// baseline (speedup 1.0000x reference)
#include <cuda_runtime.h>
#include <cuda_fp16.h>
#include <cstdint>

// ---------------------------------------------------------------------------
// Problem constants
// ---------------------------------------------------------------------------
#define NTOK   4096
#define HID    1152
#define NHEAD  16
#define HDIM   72
#define QUART  18
#define LOG2E  1.4426950408889634f

__device__ __forceinline__ float ex2f(float x) {
    float y; asm("ex2.approx.f32 %0, %1;" : "=f"(y) : "f"(x)); return y;
}
__device__ __forceinline__ uint32_t smem_u32(const void* p) {
    uint32_t a; asm("{ .reg .u64 t; cvta.to.shared.u64 t, %1; cvt.u32.u64 %0, t; }" : "=r"(a) : "l"(p));
    return a;
}

// mma.sync m16n8k16 fp16 (fp32 accum)
__device__ __forceinline__ void mma_f16(float* d, const uint32_t* a, const uint32_t* b,
                                        const float* c) {
    asm volatile(
        "mma.sync.aligned.m16n8k16.row.col.f32.f16.f16.f32 "
        "{%0,%1,%2,%3}, {%4,%5,%6,%7}, {%8,%9}, {%10,%11,%12,%13};"
        : "=f"(d[0]), "=f"(d[1]), "=f"(d[2]), "=f"(d[3])
        : "r"(a[0]), "r"(a[1]), "r"(a[2]), "r"(a[3]), "r"(b[0]), "r"(b[1]),
          "f"(c[0]), "f"(c[1]), "f"(c[2]), "f"(c[3]));
}

// mma.sync m16n8k16 fp16 with FP16 accumulators (corrections)
__device__ __forceinline__ void mma_f16acc(uint32_t* d, const uint32_t* a,
                                           const uint32_t* b, const uint32_t* c) {
    asm volatile(
        "mma.sync.aligned.m16n8k16.row.col.f16.f16.f16.f16 "
        "{%0,%1}, {%2,%3,%4,%5}, {%6,%7}, {%8,%9};"
        : "=r"(d[0]), "=r"(d[1])
        : "r"(a[0]), "r"(a[1]), "r"(a[2]), "r"(a[3]), "r"(b[0]), "r"(b[1]),
          "r"(c[0]), "r"(c[1]));
}

// ldmatrix x4 (b16)
__device__ __forceinline__ void ldsm4(uint32_t* r, uint32_t a) {
    asm volatile("ldmatrix.sync.aligned.m8n8.x4.shared.b16 {%0,%1,%2,%3}, [%4];"
        : "=r"(r[0]), "=r"(r[1]), "=r"(r[2]), "=r"(r[3]) : "r"(a));
}

// cp.async helpers
__device__ __forceinline__ void cpa16(uint32_t s, const void* g) {
    asm volatile("cp.async.cg.shared.global [%0], [%1], 16;" :: "r"(s), "l"(g));
}
#define CPA_COMMIT() asm volatile("cp.async.commit_group;" ::: "memory")
#define CPA_WAIT1()  asm volatile("cp.async.wait_group 1;" ::: "memory")
#define CPA_WAIT0()  asm volatile("cp.async.wait_group 0;" ::: "memory")

// ---------------------------------------------------------------------------
// Scratch buffers
// ---------------------------------------------------------------------------
__device__ float  g_bufQ[NTOK * HID];
__device__ float  g_bufK[NTOK * HID];
__device__ float  g_bufV[NTOK * HID];
__device__ __half g_Xhi[NTOK * HID];
__device__ __half g_Xlo[NTOK * HID];
__device__ __half g_WqThi[HID * HID];
__device__ __half g_WqTlo[HID * HID];
__device__ __half g_WkThi[HID * HID];
__device__ __half g_WkTlo[HID * HID];
__device__ __half g_WvThi[HID * HID];
__device__ __half g_WvTlo[HID * HID];
__device__ __half g_WoThi[HID * HID];
__device__ __half g_WoTlo[HID * HID];
__device__ __half g_Ohi[NTOK * HID];
__device__ __half g_Olo[NTOK * HID];
__device__ __half g_Qh[NHEAD * NTOK * 80];
__device__ __half g_Kh[NHEAD * NTOK * 80];
__device__ __half g_VTh[NHEAD * HDIM * NTOK];

// ---------------------------------------------------------------------------
// splitX: fp32 -> hi/lo fp16, float4-vectorized
// ---------------------------------------------------------------------------
__global__ __launch_bounds__(256) void splitX(const float* __restrict__ X,
                                              __half* __restrict__ Xhi,
                                              __half* __restrict__ Xlo) {
    int i = blockIdx.x * 256 + threadIdx.x;
    float4 v = ((const float4*)X)[i];
    __half h0 = __float2half(v.x), h1 = __float2half(v.y);
    __half h2 = __float2half(v.z), h3 = __float2half(v.w);
    ((__half2*)Xhi)[2 * i]     = __halves2half2(h0, h1);
    ((__half2*)Xhi)[2 * i + 1] = __halves2half2(h2, h3);
    ((__half2*)Xlo)[2 * i]     = __halves2half2(__float2half(v.x - __half2float(h0)),
                                                __float2half(v.y - __half2float(h1)));
    ((__half2*)Xlo)[2 * i + 1] = __halves2half2(__float2half(v.z - __half2float(h2)),
                                                __float2half(v.w - __half2float(h3)));
}

// ---------------------------------------------------------------------------
// splitWT4: four W[k][n] fp32 -> WT[n][k] hi/lo fp16, one launch (z = which)
// ---------------------------------------------------------------------------
__global__ __launch_bounds__(256) void splitWT4(
    const float* __restrict__ W0, __half* __restrict__ H0, __half* __restrict__ L0,
    const float* __restrict__ W1, __half* __restrict__ H1, __half* __restrict__ L1,
    const float* __restrict__ W2, __half* __restrict__ H2, __half* __restrict__ L2,
    const float* __restrict__ W3, __half* __restrict__ H3, __half* __restrict__ L3) {
    __shared__ float tile[32][33];
    const float* W; __half* WThi; __half* WTlo;
    switch (blockIdx.z) {
        case 0:  W = W0; WThi = H0; WTlo = L0; break;
        case 1:  W = W1; WThi = H1; WTlo = L1; break;
        case 2:  W = W2; WThi = H2; WTlo = L2; break;
        default: W = W3; WThi = H3; WTlo = L3; break;
    }
    const int k0 = blockIdx.y * 32, n0 = blockIdx.x * 32;
    const int tx = threadIdx.x & 31, ty = threadIdx.x >> 5;
    for (int i = ty; i < 32; i += 8)
        tile[i][tx] = W[(size_t)(k0 + i) * HID + n0 + tx];
    __syncthreads();
    for (int i = ty; i < 32; i += 8) {
        float v = tile[tx][i];
        __half h = __float2half(v);
        WThi[(size_t)(n0 + i) * HID + k0 + tx] = h;
        WTlo[(size_t)(n0 + i) * HID + k0 + tx] = __float2half(v - __half2float(h));
    }
}

// ---------------------------------------------------------------------------
// gemm16 (R14 ldmatrix version): 256 thr, warp 64x32, hi*hi -> fp32 acc,
// corrections -> fp16 acc.
// ---------------------------------------------------------------------------
#define GSTR 40
#define GASZ (128 * GSTR)

__global__ __launch_bounds__(256, 1) void gemm16(const __half* __restrict__ Ahi,
                                                 const __half* __restrict__ Alo,
                                                 const __half* __restrict__ BThi,
                                                 const __half* __restrict__ BTlo,
                                                 float* __restrict__ C) {
    extern __shared__ __half gs[];
    const int tid = threadIdx.x;
    const int warp = tid >> 5, lane = tid & 31;
    const int g = lane >> 2, t = lane & 3;
    const int wm = (warp >> 2) * 64, wn = (warp & 3) * 32;
    const int m0 = blockIdx.y * 128, n0 = blockIdx.x * 128;
    const uint32_t gsu = smem_u32(gs);

    const int lane7 = lane & 7;
    const int arow = lane7 + ((lane >> 3) & 1) * 8;
    const int akad = (lane >> 4) * 8;
    const int brow = (lane >> 4) * 8 + lane7;
    const int bkad = ((lane >> 3) & 1) * 8;

    uint32_t soff[8];
    const __half* gsrc[8];
#pragma unroll
    for (int i = 0; i < 8; i++) {
        int idx = tid + i * 256;
        int buf = idx >> 9, rem = idx & 511;
        int row = rem >> 2, ch = rem & 3;
        soff[i] = (buf < 2 ? buf * GASZ : 4 * GASZ + (buf - 2) * GASZ) + row * GSTR + ch * 8;
        const __half* base = (buf == 0) ? Ahi + (size_t)(m0 + row) * HID
                           : (buf == 1) ? Alo + (size_t)(m0 + row) * HID
                           : (buf == 2) ? BThi + (size_t)(n0 + row) * HID
                                        : BTlo + (size_t)(n0 + row) * HID;
        gsrc[i] = base + ch * 8;
    }

    float acc[4][4][4];
    uint32_t accc[4][4][2];
#pragma unroll
    for (int mf = 0; mf < 4; mf++)
#pragma unroll
        for (int nf = 0; nf < 4; nf++) {
#pragma unroll
            for (int j = 0; j < 4; j++) acc[mf][nf][j] = 0.f;
            accc[mf][nf][0] = 0u;
            accc[mf][nf][1] = 0u;
        }

#pragma unroll
    for (int i = 0; i < 8; i++)
        cpa16(smem_u32(gs + soff[i]), gsrc[i]);
    CPA_COMMIT();

    for (int kt = 0; kt < HID / 32; kt++) {
        const int cur = kt & 1;
        if (kt + 1 < HID / 32) {
            const uint32_t stoff = (cur ^ 1) * (2 * GASZ);
            const int knext = (kt + 1) * 32;
#pragma unroll
            for (int i = 0; i < 8; i++)
                cpa16(smem_u32(gs + soff[i] + stoff), gsrc[i] + knext);
            CPA_COMMIT();
            CPA_WAIT1();
        } else {
            CPA_WAIT0();
        }
        __syncthreads();

        const uint32_t abase = cur * (2 * GASZ);
        const uint32_t bbase = 4 * GASZ + cur * (2 * GASZ);
#pragma unroll
        for (int kk = 0; kk < 32; kk += 16) {
            uint32_t ah[4][4], al[4][4];
#pragma unroll
            for (int mf = 0; mf < 4; mf++) {
                uint32_t addr = gsu + 2u * (abase + (uint32_t)((wm + mf * 16 + arow) * GSTR
                                                              + kk + akad));
                ldsm4(ah[mf], addr);
                ldsm4(al[mf], addr + 2u * GASZ);
            }
            uint32_t bh[4][2], bl[4][2];
#pragma unroll
            for (int np = 0; np < 2; np++) {
                uint32_t addr = gsu + 2u * (bbase + (uint32_t)((wn + np * 16 + brow) * GSTR
                                                               + kk + bkad));
                uint32_t r[4];
                ldsm4(r, addr);
                bh[2 * np][0] = r[0]; bh[2 * np][1] = r[1];
                bh[2 * np + 1][0] = r[2]; bh[2 * np + 1][1] = r[3];
                ldsm4(r, addr + 2u * GASZ);
                bl[2 * np][0] = r[0]; bl[2 * np][1] = r[1];
                bl[2 * np + 1][0] = r[2]; bl[2 * np + 1][1] = r[3];
            }
#pragma unroll
            for (int mf = 0; mf < 4; mf++)
#pragma unroll
                for (int nf = 0; nf < 4; nf++) {
                    mma_f16(acc[mf][nf], ah[mf], bh[nf], acc[mf][nf]);
                    mma_f16acc(accc[mf][nf], ah[mf], bl[nf], accc[mf][nf]);
                    mma_f16acc(accc[mf][nf], al[mf], bh[nf], accc[mf][nf]);
                }
        }
        __syncthreads();
    }

#pragma unroll
    for (int mf = 0; mf < 4; mf++) {
        const int r0 = m0 + wm + mf * 16 + g;
#pragma unroll
        for (int nf = 0; nf < 4; nf++) {
            const int c = n0 + wn + nf * 8 + 2 * t;
            float2 c01 = __half22float2(*(__half2*)&accc[mf][nf][0]);
            float2 c23 = __half22float2(*(__half2*)&accc[mf][nf][1]);
            *(float2*)&C[(size_t)r0 * HID + c] =
                make_float2(acc[mf][nf][0] + c01.x, acc[mf][nf][1] + c01.y);
            *(float2*)&C[(size_t)(r0 + 8) * HID + c] =
                make_float2(acc[mf][nf][2] + c23.x, acc[mf][nf][3] + c23.y);
        }
    }
}

// ---------------------------------------------------------------------------
// norm_store for Q/K (rope, pad80)
// ---------------------------------------------------------------------------
__device__ __forceinline__ void norm_store(const float* __restrict__ src, const float* w,
                                           const float* __restrict__ cp,
                                           const float* __restrict__ sp,
                                           float* tmp, int lane,
                                           __half* __restrict__ dst, float oscale) {
    float x0 = src[lane];
    float x1 = src[lane + 32];
    float x2 = (lane < 8) ? src[lane + 64] : 0.f;
    float ss = x0 * x0 + x1 * x1 + x2 * x2;
#pragma unroll
    for (int off = 16; off; off >>= 1) ss += __shfl_xor_sync(0xffffffffu, ss, off);
    float rs = rsqrtf(ss * (1.0f / 72.0f) + 1e-6f);
    float y0 = x0 * rs, y1 = x1 * rs, y2 = x2 * rs;
    y0 *= w[lane];
    y1 *= w[lane + 32];
    if (lane < 8) y2 *= w[lane + 64];
    tmp[lane] = y0; tmp[lane + 32] = y1;
    if (lane < 8) tmp[lane + 64] = y2;
    __syncwarp();
    float ys[3] = { y0, y1, y2 };
    float fr[3] = { 0.f, 0.f, 0.f };
#pragma unroll
    for (int i = 0; i < 3; i++) {
        if (i == 2 && lane >= 8) break;
        int d = lane + 32 * i;
        int r = d % 36;
        int partner = d - r + ((r < QUART) ? r + QUART : r - QUART);
        float sgn = (r < QUART) ? -1.f : 1.f;
        fr[i] = ys[i] * cp[d] + sgn * tmp[partner] * sp[d];
    }
    dst[lane] = __float2half(fr[0] * oscale);
    dst[lane + 32] = __float2half(fr[1] * oscale);
    if (lane < 8) dst[lane + 64] = __float2half(fr[2] * oscale);
    if (lane >= 8 && lane < 16) dst[64 + lane] = __float2half(0.f);
    __syncwarp();
}

__global__ __launch_bounds__(256) void normqk_kernel(
    const float* __restrict__ src,
    const float* __restrict__ cosg, const float* __restrict__ sing,
    const float* __restrict__ w, __half* __restrict__ dst, float oscale) {
    __shared__ float tmp[8][HDIM];
    int warp = threadIdx.x >> 5, lane = threadIdx.x & 31;
    int pair = blockIdx.x * 8 + warp;
    int tok = pair >> 4, head = pair & 15;
    size_t off = (size_t)tok * HID + head * HDIM;
    norm_store(src + off, w, cosg + (size_t)tok * HDIM, sing + (size_t)tok * HDIM,
               tmp[warp], lane, dst + ((size_t)head * NTOK + tok) * 80, oscale);
}

// ---------------------------------------------------------------------------
// normV fused with transpose
// ---------------------------------------------------------------------------
#define VTPAD 76
__global__ __launch_bounds__(256) void normv_fused(const float* __restrict__ V,
                                                   __half* __restrict__ VTh) {
    __shared__ __half vt[64][VTPAD];
    const int warp = threadIdx.x >> 5, lane = threadIdx.x & 31;
    const int h = blockIdx.y;
    const int tb = blockIdx.x * 64;
#pragma unroll
    for (int i = 0; i < 8; i++) {
        int tl = warp * 8 + i;
        const float* src = V + (size_t)(tb + tl) * HID + h * HDIM;
        float x0 = src[lane];
        float x1 = src[lane + 32];
        float x2 = (lane < 8) ? src[lane + 64] : 0.f;
        float ss = x0 * x0 + x1 * x1 + x2 * x2;
#pragma unroll
        for (int off = 16; off; off >>= 1) ss += __shfl_xor_sync(0xffffffffu, ss, off);
        float rs = rsqrtf(ss * (1.0f / 72.0f) + 1e-6f);
        vt[tl][lane] = __float2half(x0 * rs);
        vt[tl][lane + 32] = __float2half(x1 * rs);
        if (lane < 8) vt[tl][lane + 64] = __float2half(x2 * rs);
    }
    __syncthreads();
    for (int i = threadIdx.x; i < HDIM * 32; i += 256) {
        int d = i >> 5, tp = i & 31;
        __half2 v = __halves2half2(vt[2 * tp][d], vt[2 * tp + 1][d]);
        *(__half2*)(VTh + ((size_t)h * HDIM + d) * NTOK + tb + 2 * tp) = v;
    }
}

// ---------------------------------------------------------------------------
// Flash attention R15: 128 thr = 4 warps, 2 m-tiles/warp, QPB=128,
// __launch_bounds__(128,2) -> 2 CTAs/SM (296 concurrent over 512 blocks)
// to erase the wave-quantization tail. Per-warp dataflow identical to R14.
// ---------------------------------------------------------------------------
#define TKEY 64
#define KSTR 88
#define VSTR 72
#define QPB  128

__global__ __launch_bounds__(128, 2) void attn_mma(const __half* __restrict__ Qh,
                                                   const __half* __restrict__ Kh,
                                                   const __half* __restrict__ VTh,
                                                   __half* __restrict__ Ohi,
                                                   __half* __restrict__ Olo) {
    __shared__ __half Ks[2][TKEY][KSTR];
    __shared__ __half VTs[2][HDIM][VSTR];

    const int tid = threadIdx.x;
    const int warp = tid >> 5, lane = tid & 31;
    const int g = lane >> 2, t = lane & 3;
    const int h = blockIdx.y;
    const int qbase = blockIdx.x * QPB + warp * 32;

    // zero K pad (halves 72..79), both stages: 512 words over 128 threads
    for (int i = tid; i < 512; i += 128) {
        int st = i >> 8, rem = i & 255;
        int row = rem >> 2, c = rem & 3;
        *(uint32_t*)&Ks[st][row][72 + 2 * c] = 0u;
    }

    // cp.async chunk mapping: 1152 chunks over 128 threads = 9 each (exact)
    int kind[9], ra[9], rc[9];
#pragma unroll
    for (int i = 0; i < 9; i++) {
        int idx = tid + i * 128;
        if (idx < 576) { kind[i] = 0; ra[i] = idx / 9; rc[i] = idx % 9; }
        else           { kind[i] = 1; ra[i] = (idx - 576) / 8; rc[i] = (idx - 576) % 8; }
    }

    const __half* kgb = Kh + (size_t)h * NTOK * 80;
    const __half* vgb = VTh + (size_t)h * HDIM * NTOK;

    uint32_t qf0[5][4], qf1[5][4];
    {
        const __half* a0 = Qh + ((size_t)h * NTOK + qbase + g) * 80;
        const __half* a1 = a0 + 8 * 80;
        const __half* b0 = a0 + 16 * 80;
        const __half* b1 = a0 + 24 * 80;
#pragma unroll
        for (int c = 0; c < 5; c++) {
            int d0 = 16 * c + 2 * t;
            qf0[c][0] = *(const uint32_t*)(a0 + d0);
            qf0[c][1] = *(const uint32_t*)(a1 + d0);
            qf0[c][2] = *(const uint32_t*)(a0 + d0 + 8);
            qf0[c][3] = *(const uint32_t*)(a1 + d0 + 8);
            qf1[c][0] = *(const uint32_t*)(b0 + d0);
            qf1[c][1] = *(const uint32_t*)(b1 + d0);
            qf1[c][2] = *(const uint32_t*)(b0 + d0 + 8);
            qf1[c][3] = *(const uint32_t*)(b1 + d0 + 8);
        }
    }

    float of0[9][4], of1[9][4];
#pragma unroll
    for (int n = 0; n < 9; n++)
#pragma unroll
        for (int j = 0; j < 4; j++) { of0[n][j] = 0.f; of1[n][j] = 0.f; }
    float m00 = -INFINITY, m01 = -INFINITY, l00 = 0.f, l01 = 0.f;
    float m10 = -INFINITY, m11 = -INFINITY, l10 = 0.f, l11 = 0.f;

#pragma unroll
    for (int i = 0; i < 9; i++) {
        if (kind[i] == 0)
            cpa16(smem_u32(&Ks[0][ra[i]][rc[i] * 8]), kgb + ra[i] * 80 + rc[i] * 8);
        else
            cpa16(smem_u32(&VTs[0][ra[i]][rc[i] * 8]), vgb + (size_t)ra[i] * NTOK + rc[i] * 8);
    }
    CPA_COMMIT();

    for (int tt = 0; tt < NTOK / TKEY; tt++) {
        const int cur = tt & 1;
        if (tt + 1 < NTOK / TKEY) {
            const int nxt = cur ^ 1;
            const __half* kg = kgb + (size_t)(tt + 1) * TKEY * 80;
            const __half* vg = vgb + (size_t)(tt + 1) * TKEY;
#pragma unroll
            for (int i = 0; i < 9; i++) {
                if (kind[i] == 0)
                    cpa16(smem_u32(&Ks[nxt][ra[i]][rc[i] * 8]), kg + ra[i] * 80 + rc[i] * 8);
                else
                    cpa16(smem_u32(&VTs[nxt][ra[i]][rc[i] * 8]), vg + (size_t)ra[i] * NTOK + rc[i] * 8);
            }
            CPA_COMMIT();
            CPA_WAIT1();
        } else {
            CPA_WAIT0();
        }
        __syncthreads();

        float s0[8][4], s1[8][4];
#pragma unroll
        for (int n = 0; n < 8; n++) {
            s0[n][0] = s0[n][1] = s0[n][2] = s0[n][3] = 0.f;
            s1[n][0] = s1[n][1] = s1[n][2] = s1[n][3] = 0.f;
            const int key = n * 8 + g;
#pragma unroll
            for (int c = 0; c < 5; c++) {
                const int d0 = 16 * c + 2 * t;
                uint32_t b[2];
                b[0] = *(const uint32_t*)&Ks[cur][key][d0];
                b[1] = *(const uint32_t*)&Ks[cur][key][d0 + 8];
                mma_f16(s0[n], qf0[c], b, s0[n]);
                mma_f16(s1[n], qf1[c], b, s1[n]);
            }
        }

        uint32_t p00[8], p01[8];
        {
            float rm0 = -INFINITY, rm1 = -INFINITY;
#pragma unroll
            for (int n = 0; n < 8; n++) {
                rm0 = fmaxf(rm0, fmaxf(s0[n][0], s0[n][1]));
                rm1 = fmaxf(rm1, fmaxf(s0[n][2], s0[n][3]));
            }
            rm0 = fmaxf(rm0, __shfl_xor_sync(0xffffffffu, rm0, 1));
            rm0 = fmaxf(rm0, __shfl_xor_sync(0xffffffffu, rm0, 2));
            rm1 = fmaxf(rm1, __shfl_xor_sync(0xffffffffu, rm1, 1));
            rm1 = fmaxf(rm1, __shfl_xor_sync(0xffffffffu, rm1, 2));
            float nm0 = fmaxf(m00, rm0), nm1 = fmaxf(m01, rm1);
            float corr0 = ex2f(m00 - nm0), corr1 = ex2f(m01 - nm1);
            m00 = nm0; m01 = nm1;
            float rs0 = 0.f, rs1 = 0.f;
#pragma unroll
            for (int n = 0; n < 8; n++) {
                float p0 = ex2f(s0[n][0] - m00);
                float p1 = ex2f(s0[n][1] - m00);
                float p2 = ex2f(s0[n][2] - m01);
                float p3 = ex2f(s0[n][3] - m01);
                __half2 h0 = __floats2half2_rn(p0, p1);
                __half2 h1 = __floats2half2_rn(p2, p3);
                p00[n] = *(uint32_t*)&h0;
                p01[n] = *(uint32_t*)&h1;
                float2 r0 = __half22float2(h0);
                float2 r1 = __half22float2(h1);
                rs0 += r0.x + r0.y;
                rs1 += r1.x + r1.y;
            }
            rs0 += __shfl_xor_sync(0xffffffffu, rs0, 1);
            rs0 += __shfl_xor_sync(0xffffffffu, rs0, 2);
            rs1 += __shfl_xor_sync(0xffffffffu, rs1, 1);
            rs1 += __shfl_xor_sync(0xffffffffu, rs1, 2);
            if (__all_sync(0xffffffffu, (corr0 == 1.f) && (corr1 == 1.f))) {
                l00 = l00 + rs0;
                l01 = l01 + rs1;
            } else {
                l00 = l00 * corr0 + rs0;
                l01 = l01 * corr1 + rs1;
#pragma unroll
                for (int n = 0; n < 9; n++) {
                    of0[n][0] *= corr0; of0[n][1] *= corr0;
                    of0[n][2] *= corr1; of0[n][3] *= corr1;
                }
            }
        }
        uint32_t p10[8], p11[8];
        {
            float rm0 = -INFINITY, rm1 = -INFINITY;
#pragma unroll
            for (int n = 0; n < 8; n++) {
                rm0 = fmaxf(rm0, fmaxf(s1[n][0], s1[n][1]));
                rm1 = fmaxf(rm1, fmaxf(s1[n][2], s1[n][3]));
            }
            rm0 = fmaxf(rm0, __shfl_xor_sync(0xffffffffu, rm0, 1));
            rm0 = fmaxf(rm0, __shfl_xor_sync(0xffffffffu, rm0, 2));
            rm1 = fmaxf(rm1, __shfl_xor_sync(0xffffffffu, rm1, 1));
            rm1 = fmaxf(rm1, __shfl_xor_sync(0xffffffffu, rm1, 2));
            float nm0 = fmaxf(m10, rm0), nm1 = fmaxf(m11, rm1);
            float corr0 = ex2f(m10 - nm0), corr1 = ex2f(m11 - nm1);
            m10 = nm0; m11 = nm1;
            float rs0 = 0.f, rs1 = 0.f;
#pragma unroll
            for (int n = 0; n < 8; n++) {
                float p0 = ex2f(s1[n][0] - m10);
                float p1 = ex2f(s1[n][1] - m10);
                float p2 = ex2f(s1[n][2] - m11);
                float p3 = ex2f(s1[n][3] - m11);
                __half2 h0 = __floats2half2_rn(p0, p1);
                __half2 h1 = __floats2half2_rn(p2, p3);
                p10[n] = *(uint32_t*)&h0;
                p11[n] = *(uint32_t*)&h1;
                float2 r0 = __half22float2(h0);
                float2 r1 = __half22float2(h1);
                rs0 += r0.x + r0.y;
                rs1 += r1.x + r1.y;
            }
            rs0 += __shfl_xor_sync(0xffffffffu, rs0, 1);
            rs0 += __shfl_xor_sync(0xffffffffu, rs0, 2);
            rs1 += __shfl_xor_sync(0xffffffffu, rs1, 1);
            rs1 += __shfl_xor_sync(0xffffffffu, rs1, 2);
            if (__all_sync(0xffffffffu, (corr0 == 1.f) && (corr1 == 1.f))) {
                l10 = l10 + rs0;
                l11 = l11 + rs1;
            } else {
                l10 = l10 * corr0 + rs0;
                l11 = l11 * corr1 + rs1;
#pragma unroll
                for (int n = 0; n < 9; n++) {
                    of1[n][0] *= corr0; of1[n][1] *= corr0;
                    of1[n][2] *= corr1; of1[n][3] *= corr1;
                }
            }
        }

#pragma unroll
        for (int kc = 0; kc < 4; kc++) {
            uint32_t a0[4] = { p00[2 * kc], p01[2 * kc], p00[2 * kc + 1], p01[2 * kc + 1] };
            uint32_t a1[4] = { p10[2 * kc], p11[2 * kc], p10[2 * kc + 1], p11[2 * kc + 1] };
#pragma unroll
            for (int nt = 0; nt < 9; nt++) {
                const int d = 8 * nt + g;
                const int key = 16 * kc + 2 * t;
                uint32_t b[2];
                b[0] = *(const uint32_t*)&VTs[cur][d][key];
                b[1] = *(const uint32_t*)&VTs[cur][d][key + 8];
                mma_f16(of0[nt], a0, b, of0[nt]);
                mma_f16(of1[nt], a1, b, of1[nt]);
            }
        }
        __syncthreads();
    }

    // ---- epilogue: write hi/lo fp16 ----
    {
        float inv[4] = { 1.0f / l00, 1.0f / l01, 1.0f / l10, 1.0f / l11 };
        const float* ofs[4][9];
#pragma unroll
        for (int nt = 0; nt < 9; nt++) {
            ofs[0][nt] = &of0[nt][0];
            ofs[1][nt] = &of0[nt][2];
            ofs[2][nt] = &of1[nt][0];
            ofs[3][nt] = &of1[nt][2];
        }
#pragma unroll
        for (int r = 0; r < 4; r++) {
            size_t rowoff = (size_t)(qbase + 8 * r + g) * HID + h * HDIM;
#pragma unroll
            for (int nt = 0; nt < 9; nt++) {
                int col = 8 * nt + 2 * t;
                float v0 = ofs[r][nt][0] * inv[r];
                float v1 = ofs[r][nt][1] * inv[r];
                __half h0 = __float2half(v0), h1 = __float2half(v1);
                *(__half2*)(Ohi + rowoff + col) = __halves2half2(h0, h1);
                *(__half2*)(Olo + rowoff + col) =
                    __halves2half2(__float2half(v0 - __half2float(h0)),
                                   __float2half(v1 - __half2float(h1)));
            }
        }
    }
}

// ---------------------------------------------------------------------------
// Launch: stream-forked schedule (R13).
// ---------------------------------------------------------------------------
extern "C" void kernel_launch(void* const* d_in, const int* in_sizes, int n_in,
                              void* d_out, int out_size) {
    const float* X  = (const float*)d_in[0];
    const float* cs = (const float*)d_in[1];
    const float* sn = (const float*)d_in[2];
    const float* Wq = (const float*)d_in[3];
    const float* Wk = (const float*)d_in[4];
    const float* Wv = (const float*)d_in[5];
    const float* Wo = (const float*)d_in[6];
    const float* qs = (const float*)d_in[7];
    const float* ks = (const float*)d_in[8];
    float* out = (float*)d_out;

    static float *bq = nullptr, *bk = nullptr, *bv = nullptr;
    static __half *xhi, *xlo, *wqh, *wql, *wkh, *wkl, *wvh, *wvl, *woh, *wol;
    static __half *ohi, *olo, *qh, *kh, *vth;
    static cudaStream_t s1;
    static cudaEvent_t evRoot, evWT, evGV, evGK, evGQ, evS1;
    if (!bq) {
        cudaGetSymbolAddress((void**)&bq, g_bufQ);
        cudaGetSymbolAddress((void**)&bk, g_bufK);
        cudaGetSymbolAddress((void**)&bv, g_bufV);
        cudaGetSymbolAddress((void**)&xhi, g_Xhi);
        cudaGetSymbolAddress((void**)&xlo, g_Xlo);
        cudaGetSymbolAddress((void**)&wqh, g_WqThi);
        cudaGetSymbolAddress((void**)&wql, g_WqTlo);
        cudaGetSymbolAddress((void**)&wkh, g_WkThi);
        cudaGetSymbolAddress((void**)&wkl, g_WkTlo);
        cudaGetSymbolAddress((void**)&wvh, g_WvThi);
        cudaGetSymbolAddress((void**)&wvl, g_WvTlo);
        cudaGetSymbolAddress((void**)&woh, g_WoThi);
        cudaGetSymbolAddress((void**)&wol, g_WoTlo);
        cudaGetSymbolAddress((void**)&ohi, g_Ohi);
        cudaGetSymbolAddress((void**)&olo, g_Olo);
        cudaGetSymbolAddress((void**)&qh, g_Qh);
        cudaGetSymbolAddress((void**)&kh, g_Kh);
        cudaGetSymbolAddress((void**)&vth, g_VTh);
        cudaFuncSetAttribute(gemm16, cudaFuncAttributeMaxDynamicSharedMemorySize, 81920);
        cudaStreamCreateWithFlags(&s1, cudaStreamNonBlocking);
        cudaEventCreateWithFlags(&evRoot, cudaEventDisableTiming);
        cudaEventCreateWithFlags(&evWT, cudaEventDisableTiming);
        cudaEventCreateWithFlags(&evGV, cudaEventDisableTiming);
        cudaEventCreateWithFlags(&evGK, cudaEventDisableTiming);
        cudaEventCreateWithFlags(&evGQ, cudaEventDisableTiming);
        cudaEventCreateWithFlags(&evS1, cudaEventDisableTiming);
    }

    cudaEventRecord(evRoot, 0);
    cudaStreamWaitEvent(s1, evRoot, 0);

    splitX<<<(NTOK * HID) / 1024, 256>>>(X, xhi, xlo);
    splitWT4<<<dim3(36, 36, 4), 256, 0, s1>>>(Wq, wqh, wql, Wk, wkh, wkl,
                                              Wv, wvh, wvl, Wo, woh, wol);
    cudaEventRecord(evWT, s1);
    cudaStreamWaitEvent(0, evWT, 0);

    dim3 gg(HID / 128, NTOK / 128);   // (9, 32)
    gemm16<<<gg, 256, 81920>>>(xhi, xlo, wvh, wvl, bv);
    cudaEventRecord(evGV, 0);
    gemm16<<<gg, 256, 81920>>>(xhi, xlo, wkh, wkl, bk);
    cudaEventRecord(evGK, 0);
    gemm16<<<gg, 256, 81920>>>(xhi, xlo, wqh, wql, bq);
    cudaEventRecord(evGQ, 0);

    cudaStreamWaitEvent(s1, evGV, 0);
    normv_fused<<<dim3(NTOK / 64, NHEAD), 256, 0, s1>>>(bv, vth);
    cudaStreamWaitEvent(s1, evGK, 0);
    normqk_kernel<<<(NTOK * NHEAD) / 8, 256, 0, s1>>>(bk, cs, sn, ks, kh, 1.0f);
    cudaStreamWaitEvent(s1, evGQ, 0);
    normqk_kernel<<<(NTOK * NHEAD) / 8, 256, 0, s1>>>(bq, cs, sn, qs, qh, LOG2E);
    cudaEventRecord(evS1, s1);

    cudaStreamWaitEvent(0, evS1, 0);
    attn_mma<<<dim3(NTOK / QPB, NHEAD), 128>>>(qh, kh, vth, ohi, olo);
    gemm16<<<gg, 256, 81920>>>(ohi, olo, woh, wol, out);
}

// round 16
// speedup vs baseline: 1.0406x; 1.0406x over previous
#include <cuda_runtime.h>
#include <cuda_fp16.h>
#include <cstdint>

// ---------------------------------------------------------------------------
// Problem constants
// ---------------------------------------------------------------------------
#define NTOK   4096
#define HID    1152
#define NHEAD  16
#define HDIM   72
#define QUART  18
#define LOG2E  1.4426950408889634f

__device__ __forceinline__ float ex2f(float x) {
    float y; asm("ex2.approx.f32 %0, %1;" : "=f"(y) : "f"(x)); return y;
}
__device__ __forceinline__ uint32_t smem_u32(const void* p) {
    uint32_t a; asm("{ .reg .u64 t; cvta.to.shared.u64 t, %1; cvt.u32.u64 %0, t; }" : "=r"(a) : "l"(p));
    return a;
}

// mma.sync m16n8k16 fp16 (fp32 accum)
__device__ __forceinline__ void mma_f16(float* d, const uint32_t* a, const uint32_t* b,
                                        const float* c) {
    asm volatile(
        "mma.sync.aligned.m16n8k16.row.col.f32.f16.f16.f32 "
        "{%0,%1,%2,%3}, {%4,%5,%6,%7}, {%8,%9}, {%10,%11,%12,%13};"
        : "=f"(d[0]), "=f"(d[1]), "=f"(d[2]), "=f"(d[3])
        : "r"(a[0]), "r"(a[1]), "r"(a[2]), "r"(a[3]), "r"(b[0]), "r"(b[1]),
          "f"(c[0]), "f"(c[1]), "f"(c[2]), "f"(c[3]));
}

// mma.sync m16n8k16 fp16 with FP16 accumulators (corrections)
__device__ __forceinline__ void mma_f16acc(uint32_t* d, const uint32_t* a,
                                           const uint32_t* b, const uint32_t* c) {
    asm volatile(
        "mma.sync.aligned.m16n8k16.row.col.f16.f16.f16.f16 "
        "{%0,%1}, {%2,%3,%4,%5}, {%6,%7}, {%8,%9};"
        : "=r"(d[0]), "=r"(d[1])
        : "r"(a[0]), "r"(a[1]), "r"(a[2]), "r"(a[3]), "r"(b[0]), "r"(b[1]),
          "r"(c[0]), "r"(c[1]));
}

// ldmatrix x4 (b16)
__device__ __forceinline__ void ldsm4(uint32_t* r, uint32_t a) {
    asm volatile("ldmatrix.sync.aligned.m8n8.x4.shared.b16 {%0,%1,%2,%3}, [%4];"
        : "=r"(r[0]), "=r"(r[1]), "=r"(r[2]), "=r"(r[3]) : "r"(a));
}

// cp.async helpers
__device__ __forceinline__ void cpa16(uint32_t s, const void* g) {
    asm volatile("cp.async.cg.shared.global [%0], [%1], 16;" :: "r"(s), "l"(g));
}
#define CPA_COMMIT() asm volatile("cp.async.commit_group;" ::: "memory")
#define CPA_WAIT1()  asm volatile("cp.async.wait_group 1;" ::: "memory")
#define CPA_WAIT0()  asm volatile("cp.async.wait_group 0;" ::: "memory")

// ---------------------------------------------------------------------------
// Scratch buffers
// ---------------------------------------------------------------------------
__device__ float  g_bufQ[NTOK * HID];
__device__ float  g_bufK[NTOK * HID];
__device__ float  g_bufV[NTOK * HID];
__device__ __half g_Xhi[NTOK * HID];
__device__ __half g_Xlo[NTOK * HID];
__device__ __half g_WqThi[HID * HID];
__device__ __half g_WqTlo[HID * HID];
__device__ __half g_WkThi[HID * HID];
__device__ __half g_WkTlo[HID * HID];
__device__ __half g_WvThi[HID * HID];
__device__ __half g_WvTlo[HID * HID];
__device__ __half g_WoThi[HID * HID];
__device__ __half g_WoTlo[HID * HID];
__device__ __half g_Ohi[NTOK * HID];
__device__ __half g_Olo[NTOK * HID];
__device__ __half g_Qh[NHEAD * NTOK * 80];
__device__ __half g_Kh[NHEAD * NTOK * 80];
__device__ __half g_VTh[NHEAD * HDIM * NTOK];

// ---------------------------------------------------------------------------
// splitX: fp32 -> hi/lo fp16, float4-vectorized
// ---------------------------------------------------------------------------
__global__ __launch_bounds__(256) void splitX(const float* __restrict__ X,
                                              __half* __restrict__ Xhi,
                                              __half* __restrict__ Xlo) {
    int i = blockIdx.x * 256 + threadIdx.x;
    float4 v = ((const float4*)X)[i];
    __half h0 = __float2half(v.x), h1 = __float2half(v.y);
    __half h2 = __float2half(v.z), h3 = __float2half(v.w);
    ((__half2*)Xhi)[2 * i]     = __halves2half2(h0, h1);
    ((__half2*)Xhi)[2 * i + 1] = __halves2half2(h2, h3);
    ((__half2*)Xlo)[2 * i]     = __halves2half2(__float2half(v.x - __half2float(h0)),
                                                __float2half(v.y - __half2float(h1)));
    ((__half2*)Xlo)[2 * i + 1] = __halves2half2(__float2half(v.z - __half2float(h2)),
                                                __float2half(v.w - __half2float(h3)));
}

// ---------------------------------------------------------------------------
// splitWT4: four W[k][n] fp32 -> WT[n][k] hi/lo fp16, one launch (z = which)
// ---------------------------------------------------------------------------
__global__ __launch_bounds__(256) void splitWT4(
    const float* __restrict__ W0, __half* __restrict__ H0, __half* __restrict__ L0,
    const float* __restrict__ W1, __half* __restrict__ H1, __half* __restrict__ L1,
    const float* __restrict__ W2, __half* __restrict__ H2, __half* __restrict__ L2,
    const float* __restrict__ W3, __half* __restrict__ H3, __half* __restrict__ L3) {
    __shared__ float tile[32][33];
    const float* W; __half* WThi; __half* WTlo;
    switch (blockIdx.z) {
        case 0:  W = W0; WThi = H0; WTlo = L0; break;
        case 1:  W = W1; WThi = H1; WTlo = L1; break;
        case 2:  W = W2; WThi = H2; WTlo = L2; break;
        default: W = W3; WThi = H3; WTlo = L3; break;
    }
    const int k0 = blockIdx.y * 32, n0 = blockIdx.x * 32;
    const int tx = threadIdx.x & 31, ty = threadIdx.x >> 5;
    for (int i = ty; i < 32; i += 8)
        tile[i][tx] = W[(size_t)(k0 + i) * HID + n0 + tx];
    __syncthreads();
    for (int i = ty; i < 32; i += 8) {
        float v = tile[tx][i];
        __half h = __float2half(v);
        WThi[(size_t)(n0 + i) * HID + k0 + tx] = h;
        WTlo[(size_t)(n0 + i) * HID + k0 + tx] = __float2half(v - __half2float(h));
    }
}

// ---------------------------------------------------------------------------
// gemm16 (R14 ldmatrix version, measured 105.6us): 256 thr, warp 64x32,
// hi*hi -> fp32 acc, corrections -> fp16 acc.
// ---------------------------------------------------------------------------
#define GSTR 40
#define GASZ (128 * GSTR)

__global__ __launch_bounds__(256, 1) void gemm16(const __half* __restrict__ Ahi,
                                                 const __half* __restrict__ Alo,
                                                 const __half* __restrict__ BThi,
                                                 const __half* __restrict__ BTlo,
                                                 float* __restrict__ C) {
    extern __shared__ __half gs[];
    const int tid = threadIdx.x;
    const int warp = tid >> 5, lane = tid & 31;
    const int g = lane >> 2, t = lane & 3;
    const int wm = (warp >> 2) * 64, wn = (warp & 3) * 32;
    const int m0 = blockIdx.y * 128, n0 = blockIdx.x * 128;
    const uint32_t gsu = smem_u32(gs);

    const int lane7 = lane & 7;
    const int arow = lane7 + ((lane >> 3) & 1) * 8;
    const int akad = (lane >> 4) * 8;
    const int brow = (lane >> 4) * 8 + lane7;
    const int bkad = ((lane >> 3) & 1) * 8;

    uint32_t soff[8];
    const __half* gsrc[8];
#pragma unroll
    for (int i = 0; i < 8; i++) {
        int idx = tid + i * 256;
        int buf = idx >> 9, rem = idx & 511;
        int row = rem >> 2, ch = rem & 3;
        soff[i] = (buf < 2 ? buf * GASZ : 4 * GASZ + (buf - 2) * GASZ) + row * GSTR + ch * 8;
        const __half* base = (buf == 0) ? Ahi + (size_t)(m0 + row) * HID
                           : (buf == 1) ? Alo + (size_t)(m0 + row) * HID
                           : (buf == 2) ? BThi + (size_t)(n0 + row) * HID
                                        : BTlo + (size_t)(n0 + row) * HID;
        gsrc[i] = base + ch * 8;
    }

    float acc[4][4][4];
    uint32_t accc[4][4][2];
#pragma unroll
    for (int mf = 0; mf < 4; mf++)
#pragma unroll
        for (int nf = 0; nf < 4; nf++) {
#pragma unroll
            for (int j = 0; j < 4; j++) acc[mf][nf][j] = 0.f;
            accc[mf][nf][0] = 0u;
            accc[mf][nf][1] = 0u;
        }

#pragma unroll
    for (int i = 0; i < 8; i++)
        cpa16(smem_u32(gs + soff[i]), gsrc[i]);
    CPA_COMMIT();

    for (int kt = 0; kt < HID / 32; kt++) {
        const int cur = kt & 1;
        if (kt + 1 < HID / 32) {
            const uint32_t stoff = (cur ^ 1) * (2 * GASZ);
            const int knext = (kt + 1) * 32;
#pragma unroll
            for (int i = 0; i < 8; i++)
                cpa16(smem_u32(gs + soff[i] + stoff), gsrc[i] + knext);
            CPA_COMMIT();
            CPA_WAIT1();
        } else {
            CPA_WAIT0();
        }
        __syncthreads();

        const uint32_t abase = cur * (2 * GASZ);
        const uint32_t bbase = 4 * GASZ + cur * (2 * GASZ);
#pragma unroll
        for (int kk = 0; kk < 32; kk += 16) {
            uint32_t ah[4][4], al[4][4];
#pragma unroll
            for (int mf = 0; mf < 4; mf++) {
                uint32_t addr = gsu + 2u * (abase + (uint32_t)((wm + mf * 16 + arow) * GSTR
                                                              + kk + akad));
                ldsm4(ah[mf], addr);
                ldsm4(al[mf], addr + 2u * GASZ);
            }
            uint32_t bh[4][2], bl[4][2];
#pragma unroll
            for (int np = 0; np < 2; np++) {
                uint32_t addr = gsu + 2u * (bbase + (uint32_t)((wn + np * 16 + brow) * GSTR
                                                               + kk + bkad));
                uint32_t r[4];
                ldsm4(r, addr);
                bh[2 * np][0] = r[0]; bh[2 * np][1] = r[1];
                bh[2 * np + 1][0] = r[2]; bh[2 * np + 1][1] = r[3];
                ldsm4(r, addr + 2u * GASZ);
                bl[2 * np][0] = r[0]; bl[2 * np][1] = r[1];
                bl[2 * np + 1][0] = r[2]; bl[2 * np + 1][1] = r[3];
            }
#pragma unroll
            for (int mf = 0; mf < 4; mf++)
#pragma unroll
                for (int nf = 0; nf < 4; nf++) {
                    mma_f16(acc[mf][nf], ah[mf], bh[nf], acc[mf][nf]);
                    mma_f16acc(accc[mf][nf], ah[mf], bl[nf], accc[mf][nf]);
                    mma_f16acc(accc[mf][nf], al[mf], bh[nf], accc[mf][nf]);
                }
        }
        __syncthreads();
    }

#pragma unroll
    for (int mf = 0; mf < 4; mf++) {
        const int r0 = m0 + wm + mf * 16 + g;
#pragma unroll
        for (int nf = 0; nf < 4; nf++) {
            const int c = n0 + wn + nf * 8 + 2 * t;
            float2 c01 = __half22float2(*(__half2*)&accc[mf][nf][0]);
            float2 c23 = __half22float2(*(__half2*)&accc[mf][nf][1]);
            *(float2*)&C[(size_t)r0 * HID + c] =
                make_float2(acc[mf][nf][0] + c01.x, acc[mf][nf][1] + c01.y);
            *(float2*)&C[(size_t)(r0 + 8) * HID + c] =
                make_float2(acc[mf][nf][2] + c23.x, acc[mf][nf][3] + c23.y);
        }
    }
}

// ---------------------------------------------------------------------------
// norm_store for Q/K (rope, pad80)
// ---------------------------------------------------------------------------
__device__ __forceinline__ void norm_store(const float* __restrict__ src, const float* w,
                                           const float* __restrict__ cp,
                                           const float* __restrict__ sp,
                                           float* tmp, int lane,
                                           __half* __restrict__ dst, float oscale) {
    float x0 = src[lane];
    float x1 = src[lane + 32];
    float x2 = (lane < 8) ? src[lane + 64] : 0.f;
    float ss = x0 * x0 + x1 * x1 + x2 * x2;
#pragma unroll
    for (int off = 16; off; off >>= 1) ss += __shfl_xor_sync(0xffffffffu, ss, off);
    float rs = rsqrtf(ss * (1.0f / 72.0f) + 1e-6f);
    float y0 = x0 * rs, y1 = x1 * rs, y2 = x2 * rs;
    y0 *= w[lane];
    y1 *= w[lane + 32];
    if (lane < 8) y2 *= w[lane + 64];
    tmp[lane] = y0; tmp[lane + 32] = y1;
    if (lane < 8) tmp[lane + 64] = y2;
    __syncwarp();
    float ys[3] = { y0, y1, y2 };
    float fr[3] = { 0.f, 0.f, 0.f };
#pragma unroll
    for (int i = 0; i < 3; i++) {
        if (i == 2 && lane >= 8) break;
        int d = lane + 32 * i;
        int r = d % 36;
        int partner = d - r + ((r < QUART) ? r + QUART : r - QUART);
        float sgn = (r < QUART) ? -1.f : 1.f;
        fr[i] = ys[i] * cp[d] + sgn * tmp[partner] * sp[d];
    }
    dst[lane] = __float2half(fr[0] * oscale);
    dst[lane + 32] = __float2half(fr[1] * oscale);
    if (lane < 8) dst[lane + 64] = __float2half(fr[2] * oscale);
    if (lane >= 8 && lane < 16) dst[64 + lane] = __float2half(0.f);
    __syncwarp();
}

__global__ __launch_bounds__(256) void normqk_kernel(
    const float* __restrict__ src,
    const float* __restrict__ cosg, const float* __restrict__ sing,
    const float* __restrict__ w, __half* __restrict__ dst, float oscale) {
    __shared__ float tmp[8][HDIM];
    int warp = threadIdx.x >> 5, lane = threadIdx.x & 31;
    int pair = blockIdx.x * 8 + warp;
    int tok = pair >> 4, head = pair & 15;
    size_t off = (size_t)tok * HID + head * HDIM;
    norm_store(src + off, w, cosg + (size_t)tok * HDIM, sing + (size_t)tok * HDIM,
               tmp[warp], lane, dst + ((size_t)head * NTOK + tok) * 80, oscale);
}

// ---------------------------------------------------------------------------
// normV fused with transpose
// ---------------------------------------------------------------------------
#define VTPAD 76
__global__ __launch_bounds__(256) void normv_fused(const float* __restrict__ V,
                                                   __half* __restrict__ VTh) {
    __shared__ __half vt[64][VTPAD];
    const int warp = threadIdx.x >> 5, lane = threadIdx.x & 31;
    const int h = blockIdx.y;
    const int tb = blockIdx.x * 64;
#pragma unroll
    for (int i = 0; i < 8; i++) {
        int tl = warp * 8 + i;
        const float* src = V + (size_t)(tb + tl) * HID + h * HDIM;
        float x0 = src[lane];
        float x1 = src[lane + 32];
        float x2 = (lane < 8) ? src[lane + 64] : 0.f;
        float ss = x0 * x0 + x1 * x1 + x2 * x2;
#pragma unroll
        for (int off = 16; off; off >>= 1) ss += __shfl_xor_sync(0xffffffffu, ss, off);
        float rs = rsqrtf(ss * (1.0f / 72.0f) + 1e-6f);
        vt[tl][lane] = __float2half(x0 * rs);
        vt[tl][lane + 32] = __float2half(x1 * rs);
        if (lane < 8) vt[tl][lane + 64] = __float2half(x2 * rs);
    }
    __syncthreads();
    for (int i = threadIdx.x; i < HDIM * 32; i += 256) {
        int d = i >> 5, tp = i & 31;
        __half2 v = __halves2half2(vt[2 * tp][d], vt[2 * tp + 1][d]);
        *(__half2*)(VTh + ((size_t)h * HDIM + d) * NTOK + tb + 2 * tp) = v;
    }
}

// ---------------------------------------------------------------------------
// Flash attention (exact R13 version): 256 thr = 8 warps, 2 m-tiles/warp,
// QPB=256, no skip branch.
// ---------------------------------------------------------------------------
#define TKEY 64
#define KSTR 88
#define VSTR 72
#define QPB  256

__global__ __launch_bounds__(256, 1) void attn_mma(const __half* __restrict__ Qh,
                                                   const __half* __restrict__ Kh,
                                                   const __half* __restrict__ VTh,
                                                   __half* __restrict__ Ohi,
                                                   __half* __restrict__ Olo) {
    __shared__ __half Ks[2][TKEY][KSTR];
    __shared__ __half VTs[2][HDIM][VSTR];

    const int tid = threadIdx.x;
    const int warp = tid >> 5, lane = tid & 31;
    const int g = lane >> 2, t = lane & 3;
    const int h = blockIdx.y;
    const int qbase = blockIdx.x * QPB + warp * 32;

    for (int i = tid; i < 512; i += 256) {
        int st = i >> 8, rem = i & 255;
        int row = rem >> 2, c = rem & 3;
        *(uint32_t*)&Ks[st][row][72 + 2 * c] = 0u;
    }

    int kind[5], ra[5], rc[5];
#pragma unroll
    for (int i = 0; i < 5; i++) {
        int idx = tid + i * 256;
        if (idx < 576)       { kind[i] = 0; ra[i] = idx / 9; rc[i] = idx % 9; }
        else if (idx < 1152) { kind[i] = 1; ra[i] = (idx - 576) / 8; rc[i] = (idx - 576) % 8; }
        else                 { kind[i] = 2; ra[i] = 0; rc[i] = 0; }
    }

    const __half* kgb = Kh + (size_t)h * NTOK * 80;
    const __half* vgb = VTh + (size_t)h * HDIM * NTOK;

    uint32_t qf0[5][4], qf1[5][4];
    {
        const __half* a0 = Qh + ((size_t)h * NTOK + qbase + g) * 80;
        const __half* a1 = a0 + 8 * 80;
        const __half* b0 = a0 + 16 * 80;
        const __half* b1 = a0 + 24 * 80;
#pragma unroll
        for (int c = 0; c < 5; c++) {
            int d0 = 16 * c + 2 * t;
            qf0[c][0] = *(const uint32_t*)(a0 + d0);
            qf0[c][1] = *(const uint32_t*)(a1 + d0);
            qf0[c][2] = *(const uint32_t*)(a0 + d0 + 8);
            qf0[c][3] = *(const uint32_t*)(a1 + d0 + 8);
            qf1[c][0] = *(const uint32_t*)(b0 + d0);
            qf1[c][1] = *(const uint32_t*)(b1 + d0);
            qf1[c][2] = *(const uint32_t*)(b0 + d0 + 8);
            qf1[c][3] = *(const uint32_t*)(b1 + d0 + 8);
        }
    }

    float of0[9][4], of1[9][4];
#pragma unroll
    for (int n = 0; n < 9; n++)
#pragma unroll
        for (int j = 0; j < 4; j++) { of0[n][j] = 0.f; of1[n][j] = 0.f; }
    float m00 = -INFINITY, m01 = -INFINITY, l00 = 0.f, l01 = 0.f;
    float m10 = -INFINITY, m11 = -INFINITY, l10 = 0.f, l11 = 0.f;

#pragma unroll
    for (int i = 0; i < 5; i++) {
        if (kind[i] == 0)
            cpa16(smem_u32(&Ks[0][ra[i]][rc[i] * 8]), kgb + ra[i] * 80 + rc[i] * 8);
        else if (kind[i] == 1)
            cpa16(smem_u32(&VTs[0][ra[i]][rc[i] * 8]), vgb + (size_t)ra[i] * NTOK + rc[i] * 8);
    }
    CPA_COMMIT();

    for (int tt = 0; tt < NTOK / TKEY; tt++) {
        const int cur = tt & 1;
        if (tt + 1 < NTOK / TKEY) {
            const int nxt = cur ^ 1;
            const __half* kg = kgb + (size_t)(tt + 1) * TKEY * 80;
            const __half* vg = vgb + (size_t)(tt + 1) * TKEY;
#pragma unroll
            for (int i = 0; i < 5; i++) {
                if (kind[i] == 0)
                    cpa16(smem_u32(&Ks[nxt][ra[i]][rc[i] * 8]), kg + ra[i] * 80 + rc[i] * 8);
                else if (kind[i] == 1)
                    cpa16(smem_u32(&VTs[nxt][ra[i]][rc[i] * 8]), vg + (size_t)ra[i] * NTOK + rc[i] * 8);
            }
            CPA_COMMIT();
            CPA_WAIT1();
        } else {
            CPA_WAIT0();
        }
        __syncthreads();

        float s0[8][4], s1[8][4];
#pragma unroll
        for (int n = 0; n < 8; n++) {
            s0[n][0] = s0[n][1] = s0[n][2] = s0[n][3] = 0.f;
            s1[n][0] = s1[n][1] = s1[n][2] = s1[n][3] = 0.f;
            const int key = n * 8 + g;
#pragma unroll
            for (int c = 0; c < 5; c++) {
                const int d0 = 16 * c + 2 * t;
                uint32_t b[2];
                b[0] = *(const uint32_t*)&Ks[cur][key][d0];
                b[1] = *(const uint32_t*)&Ks[cur][key][d0 + 8];
                mma_f16(s0[n], qf0[c], b, s0[n]);
                mma_f16(s1[n], qf1[c], b, s1[n]);
            }
        }

        uint32_t p00[8], p01[8];
        {
            float rm0 = -INFINITY, rm1 = -INFINITY;
#pragma unroll
            for (int n = 0; n < 8; n++) {
                rm0 = fmaxf(rm0, fmaxf(s0[n][0], s0[n][1]));
                rm1 = fmaxf(rm1, fmaxf(s0[n][2], s0[n][3]));
            }
            rm0 = fmaxf(rm0, __shfl_xor_sync(0xffffffffu, rm0, 1));
            rm0 = fmaxf(rm0, __shfl_xor_sync(0xffffffffu, rm0, 2));
            rm1 = fmaxf(rm1, __shfl_xor_sync(0xffffffffu, rm1, 1));
            rm1 = fmaxf(rm1, __shfl_xor_sync(0xffffffffu, rm1, 2));
            float nm0 = fmaxf(m00, rm0), nm1 = fmaxf(m01, rm1);
            float corr0 = ex2f(m00 - nm0), corr1 = ex2f(m01 - nm1);
            m00 = nm0; m01 = nm1;
            float rs0 = 0.f, rs1 = 0.f;
#pragma unroll
            for (int n = 0; n < 8; n++) {
                float p0 = ex2f(s0[n][0] - m00);
                float p1 = ex2f(s0[n][1] - m00);
                float p2 = ex2f(s0[n][2] - m01);
                float p3 = ex2f(s0[n][3] - m01);
                __half2 h0 = __floats2half2_rn(p0, p1);
                __half2 h1 = __floats2half2_rn(p2, p3);
                p00[n] = *(uint32_t*)&h0;
                p01[n] = *(uint32_t*)&h1;
                float2 r0 = __half22float2(h0);
                float2 r1 = __half22float2(h1);
                rs0 += r0.x + r0.y;
                rs1 += r1.x + r1.y;
            }
            rs0 += __shfl_xor_sync(0xffffffffu, rs0, 1);
            rs0 += __shfl_xor_sync(0xffffffffu, rs0, 2);
            rs1 += __shfl_xor_sync(0xffffffffu, rs1, 1);
            rs1 += __shfl_xor_sync(0xffffffffu, rs1, 2);
            l00 = l00 * corr0 + rs0;
            l01 = l01 * corr1 + rs1;
#pragma unroll
            for (int n = 0; n < 9; n++) {
                of0[n][0] *= corr0; of0[n][1] *= corr0;
                of0[n][2] *= corr1; of0[n][3] *= corr1;
            }
        }
        uint32_t p10[8], p11[8];
        {
            float rm0 = -INFINITY, rm1 = -INFINITY;
#pragma unroll
            for (int n = 0; n < 8; n++) {
                rm0 = fmaxf(rm0, fmaxf(s1[n][0], s1[n][1]));
                rm1 = fmaxf(rm1, fmaxf(s1[n][2], s1[n][3]));
            }
            rm0 = fmaxf(rm0, __shfl_xor_sync(0xffffffffu, rm0, 1));
            rm0 = fmaxf(rm0, __shfl_xor_sync(0xffffffffu, rm0, 2));
            rm1 = fmaxf(rm1, __shfl_xor_sync(0xffffffffu, rm1, 1));
            rm1 = fmaxf(rm1, __shfl_xor_sync(0xffffffffu, rm1, 2));
            float nm0 = fmaxf(m10, rm0), nm1 = fmaxf(m11, rm1);
            float corr0 = ex2f(m10 - nm0), corr1 = ex2f(m11 - nm1);
            m10 = nm0; m11 = nm1;
            float rs0 = 0.f, rs1 = 0.f;
#pragma unroll
            for (int n = 0; n < 8; n++) {
                float p0 = ex2f(s1[n][0] - m10);
                float p1 = ex2f(s1[n][1] - m10);
                float p2 = ex2f(s1[n][2] - m11);
                float p3 = ex2f(s1[n][3] - m11);
                __half2 h0 = __floats2half2_rn(p0, p1);
                __half2 h1 = __floats2half2_rn(p2, p3);
                p10[n] = *(uint32_t*)&h0;
                p11[n] = *(uint32_t*)&h1;
                float2 r0 = __half22float2(h0);
                float2 r1 = __half22float2(h1);
                rs0 += r0.x + r0.y;
                rs1 += r1.x + r1.y;
            }
            rs0 += __shfl_xor_sync(0xffffffffu, rs0, 1);
            rs0 += __shfl_xor_sync(0xffffffffu, rs0, 2);
            rs1 += __shfl_xor_sync(0xffffffffu, rs1, 1);
            rs1 += __shfl_xor_sync(0xffffffffu, rs1, 2);
            l10 = l10 * corr0 + rs0;
            l11 = l11 * corr1 + rs1;
#pragma unroll
            for (int n = 0; n < 9; n++) {
                of1[n][0] *= corr0; of1[n][1] *= corr0;
                of1[n][2] *= corr1; of1[n][3] *= corr1;
            }
        }

#pragma unroll
        for (int kc = 0; kc < 4; kc++) {
            uint32_t a0[4] = { p00[2 * kc], p01[2 * kc], p00[2 * kc + 1], p01[2 * kc + 1] };
            uint32_t a1[4] = { p10[2 * kc], p11[2 * kc], p10[2 * kc + 1], p11[2 * kc + 1] };
#pragma unroll
            for (int nt = 0; nt < 9; nt++) {
                const int d = 8 * nt + g;
                const int key = 16 * kc + 2 * t;
                uint32_t b[2];
                b[0] = *(const uint32_t*)&VTs[cur][d][key];
                b[1] = *(const uint32_t*)&VTs[cur][d][key + 8];
                mma_f16(of0[nt], a0, b, of0[nt]);
                mma_f16(of1[nt], a1, b, of1[nt]);
            }
        }
        __syncthreads();
    }

    // ---- epilogue: write hi/lo fp16 ----
    {
        float inv[4] = { 1.0f / l00, 1.0f / l01, 1.0f / l10, 1.0f / l11 };
        const float* ofs[4][9];
#pragma unroll
        for (int nt = 0; nt < 9; nt++) {
            ofs[0][nt] = &of0[nt][0];
            ofs[1][nt] = &of0[nt][2];
            ofs[2][nt] = &of1[nt][0];
            ofs[3][nt] = &of1[nt][2];
        }
#pragma unroll
        for (int r = 0; r < 4; r++) {
            size_t rowoff = (size_t)(qbase + 8 * r + g) * HID + h * HDIM;
#pragma unroll
            for (int nt = 0; nt < 9; nt++) {
                int col = 8 * nt + 2 * t;
                float v0 = ofs[r][nt][0] * inv[r];
                float v1 = ofs[r][nt][1] * inv[r];
                __half h0 = __float2half(v0), h1 = __float2half(v1);
                *(__half2*)(Ohi + rowoff + col) = __halves2half2(h0, h1);
                *(__half2*)(Olo + rowoff + col) =
                    __halves2half2(__float2half(v0 - __half2float(h0)),
                                   __float2half(v1 - __half2float(h1)));
            }
        }
    }
}

// ---------------------------------------------------------------------------
// Launch: stream-forked schedule (R13).
// ---------------------------------------------------------------------------
extern "C" void kernel_launch(void* const* d_in, const int* in_sizes, int n_in,
                              void* d_out, int out_size) {
    const float* X  = (const float*)d_in[0];
    const float* cs = (const float*)d_in[1];
    const float* sn = (const float*)d_in[2];
    const float* Wq = (const float*)d_in[3];
    const float* Wk = (const float*)d_in[4];
    const float* Wv = (const float*)d_in[5];
    const float* Wo = (const float*)d_in[6];
    const float* qs = (const float*)d_in[7];
    const float* ks = (const float*)d_in[8];
    float* out = (float*)d_out;

    static float *bq = nullptr, *bk = nullptr, *bv = nullptr;
    static __half *xhi, *xlo, *wqh, *wql, *wkh, *wkl, *wvh, *wvl, *woh, *wol;
    static __half *ohi, *olo, *qh, *kh, *vth;
    static cudaStream_t s1;
    static cudaEvent_t evRoot, evWT, evGV, evGK, evGQ, evS1;
    if (!bq) {
        cudaGetSymbolAddress((void**)&bq, g_bufQ);
        cudaGetSymbolAddress((void**)&bk, g_bufK);
        cudaGetSymbolAddress((void**)&bv, g_bufV);
        cudaGetSymbolAddress((void**)&xhi, g_Xhi);
        cudaGetSymbolAddress((void**)&xlo, g_Xlo);
        cudaGetSymbolAddress((void**)&wqh, g_WqThi);
        cudaGetSymbolAddress((void**)&wql, g_WqTlo);
        cudaGetSymbolAddress((void**)&wkh, g_WkThi);
        cudaGetSymbolAddress((void**)&wkl, g_WkTlo);
        cudaGetSymbolAddress((void**)&wvh, g_WvThi);
        cudaGetSymbolAddress((void**)&wvl, g_WvTlo);
        cudaGetSymbolAddress((void**)&woh, g_WoThi);
        cudaGetSymbolAddress((void**)&wol, g_WoTlo);
        cudaGetSymbolAddress((void**)&ohi, g_Ohi);
        cudaGetSymbolAddress((void**)&olo, g_Olo);
        cudaGetSymbolAddress((void**)&qh, g_Qh);
        cudaGetSymbolAddress((void**)&kh, g_Kh);
        cudaGetSymbolAddress((void**)&vth, g_VTh);
        cudaFuncSetAttribute(gemm16, cudaFuncAttributeMaxDynamicSharedMemorySize, 81920);
        cudaStreamCreateWithFlags(&s1, cudaStreamNonBlocking);
        cudaEventCreateWithFlags(&evRoot, cudaEventDisableTiming);
        cudaEventCreateWithFlags(&evWT, cudaEventDisableTiming);
        cudaEventCreateWithFlags(&evGV, cudaEventDisableTiming);
        cudaEventCreateWithFlags(&evGK, cudaEventDisableTiming);
        cudaEventCreateWithFlags(&evGQ, cudaEventDisableTiming);
        cudaEventCreateWithFlags(&evS1, cudaEventDisableTiming);
    }

    cudaEventRecord(evRoot, 0);
    cudaStreamWaitEvent(s1, evRoot, 0);

    splitX<<<(NTOK * HID) / 1024, 256>>>(X, xhi, xlo);
    splitWT4<<<dim3(36, 36, 4), 256, 0, s1>>>(Wq, wqh, wql, Wk, wkh, wkl,
                                              Wv, wvh, wvl, Wo, woh, wol);
    cudaEventRecord(evWT, s1);
    cudaStreamWaitEvent(0, evWT, 0);

    dim3 gg(HID / 128, NTOK / 128);   // (9, 32)
    gemm16<<<gg, 256, 81920>>>(xhi, xlo, wvh, wvl, bv);
    cudaEventRecord(evGV, 0);
    gemm16<<<gg, 256, 81920>>>(xhi, xlo, wkh, wkl, bk);
    cudaEventRecord(evGK, 0);
    gemm16<<<gg, 256, 81920>>>(xhi, xlo, wqh, wql, bq);
    cudaEventRecord(evGQ, 0);

    cudaStreamWaitEvent(s1, evGV, 0);
    normv_fused<<<dim3(NTOK / 64, NHEAD), 256, 0, s1>>>(bv, vth);
    cudaStreamWaitEvent(s1, evGK, 0);
    normqk_kernel<<<(NTOK * NHEAD) / 8, 256, 0, s1>>>(bk, cs, sn, ks, kh, 1.0f);
    cudaStreamWaitEvent(s1, evGQ, 0);
    normqk_kernel<<<(NTOK * NHEAD) / 8, 256, 0, s1>>>(bq, cs, sn, qs, qh, LOG2E);
    cudaEventRecord(evS1, s1);

    cudaStreamWaitEvent(0, evS1, 0);
    attn_mma<<<dim3(NTOK / QPB, NHEAD), 256>>>(qh, kh, vth, ohi, olo);
    gemm16<<<gg, 256, 81920>>>(ohi, olo, woh, wol, out);
}